// round 11
// baseline (speedup 1.0000x reference)
#include <cuda_runtime.h>
#include <cuda_fp16.h>

#define HID   100
#define G4    400
#define SEQ   8192
#define NCLS  20
#define TB    16
#define NTL   500      // 5 K-slices x 100 units (R9 proven layout)
#define KS    20       // floats per K-slice (5*20 = 100, exact)

// scratch for x_proj, stored TRANSPOSED: xp4[t*100 + j] = (i,f,g,o) of unit j
__device__ float4 g_xp4[SEQ * HID];

__device__ __forceinline__ float tanh_a(float x) {
    float y;
    asm("tanh.approx.f32 %0, %1;" : "=f"(y) : "f"(x));
    return y;
}
// sigmoid(x) = 0.5*tanh(x/2) + 0.5  (1 MUFU instead of EX2+RCP chain)
__device__ __forceinline__ float sig_a(float x) {
    return fmaf(0.5f, tanh_a(0.5f * x), 0.5f);
}
__device__ __forceinline__ __half2 u2h(unsigned int u) {
    __half2 h;
    *(unsigned int*)&h = u;
    return h;
}

// ---------------------------------------------------------------------------
// Kernel 1: embedding gather + x_proj GEMM, TRANSPOSED output (i,f,g,o)/unit
// (full fp32 — feeds the fp32 owner tail, unchanged)
// ---------------------------------------------------------------------------
__global__ void __launch_bounds__(G4, 1)
proj_kernel(const int* __restrict__ seq, const float* __restrict__ emb,
            const float* __restrict__ W_ih, const float* __restrict__ b_ih,
            const float* __restrict__ b_hh) {
    __shared__ float es[TB * HID];
    __shared__ int   sid[TB];
    const int tid = threadIdx.x;          // gate row r = g*100 + j
    const int t0  = blockIdx.x * TB;
    const int g   = tid / HID;
    const int j   = tid - g * HID;

    if (tid < TB) sid[tid] = seq[t0 + tid];
    __syncthreads();
    for (int n = tid; n < TB * HID; n += G4) {
        int tt = n / HID, k = n % HID;
        es[n] = emb[(long long)sid[tt] * HID + k];
    }
    __syncthreads();

    float acc[TB];
#pragma unroll
    for (int tt = 0; tt < TB; tt++) acc[tt] = 0.f;

    const float4* wr4 = (const float4*)(W_ih + tid * HID);
#pragma unroll 5
    for (int m = 0; m < 25; m++) {
        float4 wv = __ldg(&wr4[m]);
#pragma unroll
        for (int tt = 0; tt < TB; tt++) {
            const float* e = es + tt * HID + 4 * m;
            acc[tt] += wv.x * e[0] + wv.y * e[1] + wv.z * e[2] + wv.w * e[3];
        }
    }
    float b = b_ih[tid] + b_hh[tid];
    float* xp = (float*)g_xp4;
#pragma unroll
    for (int tt = 0; tt < TB; tt++)
        xp[(t0 + tt) * G4 + j * 4 + g] = acc[tt] + b;   // transposed
}

// ---------------------------------------------------------------------------
// Kernel 2: LSTM recurrence — R9 skeleton; matvec switched to fp16 HFMA2
// (rt 2 => 128 MACs/SM/cyc, 2x the fp32 rate). Weights pre-converted to
// half2 in registers (40 regs). h kept in smem BOTH as fp16 (matvec feed)
// and fp32 (final FC). Two depth-5 fp16 accum chains per gate; cross-slice
// reduction, x_proj add, activations, c-chain all remain fp32.
// ---------------------------------------------------------------------------
__global__ void __launch_bounds__(NTL, 1)
lstm_kernel(const float* __restrict__ W_hh,
            const float* __restrict__ fc_w, const float* __restrict__ fc_b,
            float* __restrict__ out) {
    __shared__ __align__(16) __half h_hf[HID];   // fp16 h (matvec feed)
    __shared__ __align__(16) float  h_sh[HID];   // fp32 h (final FC)
    __shared__ __align__(16) float4 part4[NTL];
    const int tid = threadIdx.x;
    const int s   = tid / HID;            // K-slice 0..4
    const int j   = tid - s * HID;        // unit 0..99
    const bool owner = (s == 0);

    // preload weights as half2: 4 gate rows x 10 half2 of this K-slice
    unsigned int wh[40];
#pragma unroll
    for (int g = 0; g < 4; g++) {
        const float2* wrow = (const float2*)(W_hh + (g * HID + j) * HID + KS * s);
#pragma unroll
        for (int m = 0; m < 10; m++) {
            float2 v = wrow[m];
            __half2 h2 = __floats2half2_rn(v.x, v.y);
            wh[g * 10 + m] = *(unsigned int*)&h2;
        }
    }

    if (tid < HID) {
        h_sh[tid] = 0.f;
        h_hf[tid] = __float2half(0.f);
    }
    float c = 0.f;
    __syncthreads();

    float4 xq = owner ? __ldg(&g_xp4[j]) : make_float4(0.f, 0.f, 0.f, 0.f);

    for (int t = 0; t < SEQ; t++) {
        float4 xq_n;
        if (owner)
            xq_n = __ldg(&g_xp4[((t + 1) & (SEQ - 1)) * HID + j]);

        // matvec slice: 5 broadcast LDS.64 + 40 HFMA2
        // two depth-5 chains per gate (acc error containment)
        __half2 a0a = u2h(0u), a0b = u2h(0u), a1a = u2h(0u), a1b = u2h(0u);
        __half2 a2a = u2h(0u), a2b = u2h(0u), a3a = u2h(0u), a3b = u2h(0u);
        const uint2* hp = (const uint2*)(h_hf + KS * s);   // 40B slice, 8B aligned
#pragma unroll
        for (int m = 0; m < 5; m++) {
            uint2 u = hp[m];                 // all 32 lanes same addr (broadcast)
            __half2 ha = u2h(u.x), hb = u2h(u.y);
            a0a = __hfma2(u2h(wh[2 * m]),      ha, a0a);
            a0b = __hfma2(u2h(wh[2 * m + 1]),  hb, a0b);
            a1a = __hfma2(u2h(wh[10 + 2 * m]), ha, a1a);
            a1b = __hfma2(u2h(wh[11 + 2 * m]), hb, a1b);
            a2a = __hfma2(u2h(wh[20 + 2 * m]), ha, a2a);
            a2b = __hfma2(u2h(wh[21 + 2 * m]), hb, a2b);
            a3a = __hfma2(u2h(wh[30 + 2 * m]), ha, a3a);
            a3b = __hfma2(u2h(wh[31 + 2 * m]), hb, a3b);
        }
        // combine chains in fp32
        float2 f0a = __half22float2(a0a), f0b = __half22float2(a0b);
        float2 f1a = __half22float2(a1a), f1b = __half22float2(a1b);
        float2 f2a = __half22float2(a2a), f2b = __half22float2(a2b);
        float2 f3a = __half22float2(a3a), f3b = __half22float2(a3b);
        float pi = (f0a.x + f0a.y) + (f0b.x + f0b.y);
        float pf = (f1a.x + f1a.y) + (f1b.x + f1b.y);
        float pg = (f2a.x + f2a.y) + (f2b.x + f2b.y);
        float po = (f3a.x + f3a.y) + (f3b.x + f3b.y);

        if (!owner) part4[tid] = make_float4(pi, pf, pg, po);
        __syncthreads();

        if (owner) {
#pragma unroll
            for (int sp = 1; sp < 5; sp++) {
                float4 v = part4[sp * HID + j];
                pi += v.x; pf += v.y; pg += v.z; po += v.w;
            }
            pi += xq.x; pf += xq.y; pg += xq.z; po += xq.w;
            float ig = sig_a(pi);
            float fg = sig_a(pf);
            float gg = tanh_a(pg);
            float og = sig_a(po);
            c = fg * c + ig * gg;
            float hn = og * tanh_a(c);
            h_sh[j] = hn;                       // fp32 copy (final FC)
            h_hf[j] = __float2half_rn(hn);      // fp16 feed (2-byte STS, no race)
            xq = xq_n;
        }
        __syncthreads();
    }

    // final FC on fp32 h
    if (tid < NCLS) {
        float sfc = fc_b[tid];
        const float* fw = fc_w + tid * HID;
#pragma unroll 4
        for (int k = 0; k < HID; k++) sfc += fw[k] * h_sh[k];
        out[tid] = sfc;
    }
}

// ---------------------------------------------------------------------------
extern "C" void kernel_launch(void* const* d_in, const int* in_sizes, int n_in,
                              void* d_out, int out_size) {
    const int*   seq  = (const int*)d_in[0];
    const float* emb  = (const float*)d_in[1];
    const float* W_ih = (const float*)d_in[2];
    const float* W_hh = (const float*)d_in[3];
    const float* b_ih = (const float*)d_in[4];
    const float* b_hh = (const float*)d_in[5];
    const float* fc_w = (const float*)d_in[6];
    const float* fc_b = (const float*)d_in[7];
    float* out = (float*)d_out;

    proj_kernel<<<SEQ / TB, G4>>>(seq, emb, W_ih, b_ih, b_hh);
    lstm_kernel<<<1, NTL>>>(W_hh, fc_w, fc_b, out);
}

// round 12
// speedup vs baseline: 1.6823x; 1.6823x over previous
#include <cuda_runtime.h>

#define HID   100
#define G4    400
#define SEQ   8192
#define NCLS  20
#define TB    16
#define NTL   500      // 5 K-slices x 100 units; 16-warp alloc -> 128-reg cap
#define KS    20       // floats per K-slice (5*20 = 100, exact)

// scratch for x_proj, stored TRANSPOSED: xp4[t*100 + j] = (i,f,g,o) of unit j
// NOTE: i/f/o entries are PRE-HALVED (0.5x); g entry full scale.
__device__ float4 g_xp4[SEQ * HID];

__device__ __forceinline__ unsigned long long ffma2(unsigned long long a,
                                                    unsigned long long b,
                                                    unsigned long long c) {
    unsigned long long d;
    asm("fma.rn.f32x2 %0, %1, %2, %3;" : "=l"(d) : "l"(a), "l"(b), "l"(c));
    return d;
}
__device__ __forceinline__ void unpack2(unsigned long long v, float& lo, float& hi) {
    asm("mov.b64 {%0, %1}, %2;" : "=f"(lo), "=f"(hi) : "l"(v));
}
__device__ __forceinline__ unsigned long long pack2(float lo, float hi) {
    unsigned long long v;
    asm("mov.b64 %0, {%1, %2};" : "=l"(v) : "f"(lo), "f"(hi));
    return v;
}
__device__ __forceinline__ float tanh_a(float x) {
    float y;
    asm("tanh.approx.f32 %0, %1;" : "=f"(y) : "f"(x));
    return y;
}

// ---------------------------------------------------------------------------
// Kernel 1: embedding gather + x_proj GEMM, TRANSPOSED output (i,f,g,o)/unit
// i/f/o outputs pre-scaled by 0.5 (their sigmoid argument is consumed as
// tanh(0.5*pre); halving upstream removes an FMUL from the serial tail).
// ---------------------------------------------------------------------------
__global__ void __launch_bounds__(G4, 1)
proj_kernel(const int* __restrict__ seq, const float* __restrict__ emb,
            const float* __restrict__ W_ih, const float* __restrict__ b_ih,
            const float* __restrict__ b_hh) {
    __shared__ float es[TB * HID];
    __shared__ int   sid[TB];
    const int tid = threadIdx.x;          // gate row r = g*100 + j
    const int t0  = blockIdx.x * TB;
    const int g   = tid / HID;
    const int j   = tid - g * HID;

    if (tid < TB) sid[tid] = seq[t0 + tid];
    __syncthreads();
    for (int n = tid; n < TB * HID; n += G4) {
        int tt = n / HID, k = n % HID;
        es[n] = emb[(long long)sid[tt] * HID + k];
    }
    __syncthreads();

    float acc[TB];
#pragma unroll
    for (int tt = 0; tt < TB; tt++) acc[tt] = 0.f;

    const float4* wr4 = (const float4*)(W_ih + tid * HID);
#pragma unroll 5
    for (int m = 0; m < 25; m++) {
        float4 wv = __ldg(&wr4[m]);
#pragma unroll
        for (int tt = 0; tt < TB; tt++) {
            const float* e = es + tt * HID + 4 * m;
            acc[tt] += wv.x * e[0] + wv.y * e[1] + wv.z * e[2] + wv.w * e[3];
        }
    }
    float b = b_ih[tid] + b_hh[tid];
    const float sc = (g == 2) ? 1.0f : 0.5f;   // pre-halve i/f/o
    float* xp = (float*)g_xp4;
#pragma unroll
    for (int tt = 0; tt < TB; tt++)
        xp[(t0 + tt) * G4 + j * 4 + g] = sc * (acc[tt] + b);   // transposed
}

// ---------------------------------------------------------------------------
// Kernel 2: LSTM recurrence — R9 skeleton verbatim, except:
//  * i/f/o weight rows pre-halved at preload (matching halved x_proj), so
//    sigmoid = fma(0.5, tanh(p), 0.5) with no inner multiply;
//  * f-gate reduction scheduled first (critical chain: pf -> tanh -> c).
// tid = s*100 + j; thread owns 4 gate rows of unit j over K-slice
// [20s,20s+20): 40 f32x2 weight regs, spill-free.
// ---------------------------------------------------------------------------
__global__ void __launch_bounds__(NTL, 1)
lstm_kernel(const float* __restrict__ W_hh,
            const float* __restrict__ fc_w, const float* __restrict__ fc_b,
            float* __restrict__ out) {
    __shared__ __align__(16) float h_sh[HID];
    __shared__ __align__(16) float4 part4[NTL];
    const int tid = threadIdx.x;
    const int s   = tid / HID;            // K-slice 0..4
    const int j   = tid - s * HID;        // unit 0..99
    const bool owner = (s == 0);

    // preload weights: 4 gate rows x 5 float4 chunks; i/f/o rows scaled 0.5
    unsigned long long w2[40];
#pragma unroll
    for (int g = 0; g < 4; g++) {
        const float sc = (g == 2) ? 1.0f : 0.5f;
        const float* wrow = W_hh + (g * HID + j) * HID + KS * s;
#pragma unroll
        for (int m = 0; m < 5; m++) {
            float4 v = *(const float4*)(wrow + 4 * m);
            w2[g * 10 + 2 * m]     = pack2(sc * v.x, sc * v.y);
            w2[g * 10 + 2 * m + 1] = pack2(sc * v.z, sc * v.w);
        }
    }

    if (tid < HID) h_sh[tid] = 0.f;
    float c = 0.f;
    __syncthreads();

    float4 xq = owner ? __ldg(&g_xp4[j]) : make_float4(0.f, 0.f, 0.f, 0.f);

    for (int t = 0; t < SEQ; t++) {
        float4 xq_n;
        if (owner)
            xq_n = __ldg(&g_xp4[((t + 1) & (SEQ - 1)) * HID + j]);

        // matvec slice: 5 broadcast LDS.128 + 40 FFMA2, one acc per gate
        unsigned long long a0 = 0ull, a1 = 0ull, a2 = 0ull, a3 = 0ull;
        const ulonglong2* h2 = (const ulonglong2*)h_sh;
#pragma unroll
        for (int m = 0; m < 5; m++) {
            ulonglong2 hv = h2[5 * s + m];     // all 32 lanes same addr
            a0 = ffma2(w2[2 * m],      hv.x, a0);
            a0 = ffma2(w2[2 * m + 1],  hv.y, a0);
            a1 = ffma2(w2[10 + 2 * m], hv.x, a1);
            a1 = ffma2(w2[11 + 2 * m], hv.y, a1);
            a2 = ffma2(w2[20 + 2 * m], hv.x, a2);
            a2 = ffma2(w2[21 + 2 * m], hv.y, a2);
            a3 = ffma2(w2[30 + 2 * m], hv.x, a3);
            a3 = ffma2(w2[31 + 2 * m], hv.y, a3);
        }
        float l0, h0, l1, h1, l2, h2v, l3, h3;
        unpack2(a0, l0, h0);
        unpack2(a1, l1, h1);
        unpack2(a2, l2, h2v);
        unpack2(a3, l3, h3);
        float pi = l0 + h0, pf = l1 + h1, pg = l2 + h2v, po = l3 + h3;

        if (!owner) part4[tid] = make_float4(pi, pf, pg, po);
        __syncthreads();

        if (owner) {
            float4 v1 = part4[1 * HID + j];
            float4 v2 = part4[2 * HID + j];
            float4 v3 = part4[3 * HID + j];
            float4 v4 = part4[4 * HID + j];
            // f-gate first: its chain (tanh -> c -> tanh -> h) is critical
            pf += ((v1.y + v2.y) + (v3.y + v4.y)) + xq.y;
            float fg = fmaf(0.5f, tanh_a(pf), 0.5f);
            pi += ((v1.x + v2.x) + (v3.x + v4.x)) + xq.x;
            pg += ((v1.z + v2.z) + (v3.z + v4.z)) + xq.z;
            po += ((v1.w + v2.w) + (v3.w + v4.w)) + xq.w;
            float ig = fmaf(0.5f, tanh_a(pi), 0.5f);
            float gg = tanh_a(pg);
            float og = fmaf(0.5f, tanh_a(po), 0.5f);
            c = fg * c + ig * gg;
            h_sh[j] = og * tanh_a(c);
            xq = xq_n;
        }
        __syncthreads();
    }

    // final FC
    if (tid < NCLS) {
        float sfc = fc_b[tid];
        const float* fw = fc_w + tid * HID;
#pragma unroll 4
        for (int k = 0; k < HID; k++) sfc += fw[k] * h_sh[k];
        out[tid] = sfc;
    }
}

// ---------------------------------------------------------------------------
extern "C" void kernel_launch(void* const* d_in, const int* in_sizes, int n_in,
                              void* d_out, int out_size) {
    const int*   seq  = (const int*)d_in[0];
    const float* emb  = (const float*)d_in[1];
    const float* W_ih = (const float*)d_in[2];
    const float* W_hh = (const float*)d_in[3];
    const float* b_ih = (const float*)d_in[4];
    const float* b_hh = (const float*)d_in[5];
    const float* fc_w = (const float*)d_in[6];
    const float* fc_b = (const float*)d_in[7];
    float* out = (float*)d_out;

    proj_kernel<<<SEQ / TB, G4>>>(seq, emb, W_ih, b_ih, b_hh);
    lstm_kernel<<<1, NTL>>>(W_hh, fc_w, fc_b, out);
}